// round 3
// baseline (speedup 1.0000x reference)
#include <cuda_runtime.h>

#define FFT_N 4096
#define NT    64
#define DS(k) ((((k) & 7) << 3) | ((k) >> 3))   // swap octal digits of 0..63

typedef unsigned long long cplx;   // packed (float re, float im)

// ---------- packed f32x2 helpers ----------
__device__ __forceinline__ cplx cpack(float x, float y) {
    cplx r; asm("mov.b64 %0,{%1,%2};" : "=l"(r) : "f"(x), "f"(y)); return r;
}
__device__ __forceinline__ void cunp(cplx a, float& x, float& y) {
    asm("mov.b64 {%0,%1},%2;" : "=f"(x), "=f"(y) : "l"(a));
}
__device__ __forceinline__ cplx cadd(cplx a, cplx b) {
    cplx r; asm("add.rn.f32x2 %0,%1,%2;" : "=l"(r) : "l"(a), "l"(b)); return r;
}
__device__ __forceinline__ cplx cneg1() { return cpack(-1.0f, -1.0f); }
__device__ __forceinline__ cplx csub(cplx a, cplx b) {   // a - b = fma(b, -1, a)
    cplx r, n = cneg1();
    asm("fma.rn.f32x2 %0,%1,%2,%3;" : "=l"(r) : "l"(b), "l"(n), "l"(a)); return r;
}
__device__ __forceinline__ cplx cmulp(cplx a, cplx b) {  // elementwise (ax*bx, ay*by)
    cplx r; asm("mul.rn.f32x2 %0,%1,%2;" : "=l"(r) : "l"(a), "l"(b)); return r;
}
// multiply by -i (DIR=-1) or +i (DIR=+1)
template <int DIR>
__device__ __forceinline__ cplx crotI(cplx z) {
    float x, y; cunp(z, x, y);
    return (DIR < 0) ? cpack(y, -x) : cpack(-y, x);
}
// scalar complex multiply by runtime (wr, wi)
__device__ __forceinline__ cplx cmulw(cplx v, float wr, float wi) {
    float x, y; cunp(v, x, y);
    float rx = fmaf(x, wr, -(y * wi));
    float ry = fmaf(x, wi, y * wr);
    return cpack(rx, ry);
}
// multiply by forward twiddle (cr, -si); DIR=+1 conjugates
template <int DIR>
__device__ __forceinline__ cplx cmulc(cplx v, float cr, float si) {
    float ci = (DIR < 0) ? -si : si;
    return cmulw(v, cr, ci);
}

// ---------- compile-time W64 twiddle table (quarter sine) ----------
__host__ __device__ constexpr float QS(int i) {
    switch (i) {
        case 0:  return 0.0f;
        case 1:  return 0.0980171403295606f;
        case 2:  return 0.1950903220161283f;
        case 3:  return 0.2902846772544624f;
        case 4:  return 0.3826834323650898f;
        case 5:  return 0.4713967368259976f;
        case 6:  return 0.5555702330196022f;
        case 7:  return 0.6343932841636455f;
        case 8:  return 0.7071067811865476f;
        case 9:  return 0.7730104533627370f;
        case 10: return 0.8314696123025452f;
        case 11: return 0.8819212643483551f;
        case 12: return 0.9238795325112867f;
        case 13: return 0.9569403357322088f;
        case 14: return 0.9807852804032304f;
        case 15: return 0.9951847266721969f;
        default: return 1.0f;
    }
}
__host__ __device__ constexpr float S64(int m) {
    m &= 63;
    return (m <= 16) ? QS(m) : (m <= 32) ? QS(32 - m) : (m <= 48) ? -QS(m - 32) : -QS(64 - m);
}
__host__ __device__ constexpr float C64(int m) { return S64(m + 16); }

// ---------- 8-point DFT, natural order in/out ----------
template <int DIR>
__device__ __forceinline__ void dft8(cplx v[8]) {
    const float H = 0.70710678118654752f;
    cplx t0 = cadd(v[0], v[4]), t1 = csub(v[0], v[4]);
    cplx t2 = cadd(v[2], v[6]), t3 = csub(v[2], v[6]);
    cplx u0 = cadd(v[1], v[5]), u1 = csub(v[1], v[5]);
    cplx u2 = cadd(v[3], v[7]), u3 = csub(v[3], v[7]);
    cplx e0 = cadd(t0, t2), e2 = csub(t0, t2);
    cplx rt3 = crotI<DIR>(t3);
    cplx e1 = cadd(t1, rt3), e3 = csub(t1, rt3);
    cplx o0 = cadd(u0, u2), o2 = csub(u0, u2);
    cplx ru3 = crotI<DIR>(u3);
    cplx o1 = cadd(u1, ru3), o3 = csub(u1, ru3);
    cplx a1 = cmulc<DIR>(o1, H, H);    // W8^1 = (H, -H) forward
    cplx a2 = crotI<DIR>(o2);          // W8^2
    cplx a3 = cmulc<DIR>(o3, -H, H);   // W8^3 = (-H, -H) forward
    v[0] = cadd(e0, o0); v[4] = csub(e0, o0);
    v[1] = cadd(e1, a1); v[5] = csub(e1, a1);
    v[2] = cadd(e2, a2); v[6] = csub(e2, a2);
    v[3] = cadd(e3, a3); v[7] = csub(e3, a3);
}

// ---------- 64-point FFT in registers ----------
// BFORM=false: natural input  -> digit-swapped output (X[k] at v[DS(k)])
// BFORM=true : digit-swapped input (f[n] at v[DS(n)]) -> natural output
template <int DIR, bool BFORM>
__device__ __forceinline__ void fft64(cplx* v) {
    cplx t[8];
    // phase 1: dft8 over j2 for each j1
#pragma unroll
    for (int j1 = 0; j1 < 8; j1++) {
#pragma unroll
        for (int j2 = 0; j2 < 8; j2++) t[j2] = BFORM ? v[8 * j1 + j2] : v[j1 + 8 * j2];
        dft8<DIR>(t);
#pragma unroll
        for (int j2 = 0; j2 < 8; j2++) { if (BFORM) v[8 * j1 + j2] = t[j2]; else v[j1 + 8 * j2] = t[j2]; }
    }
    // mid twiddles: W64^{j1*k2}
#pragma unroll
    for (int j1 = 1; j1 < 8; j1++) {
#pragma unroll
        for (int k2 = 1; k2 < 8; k2++) {
            int m = j1 * k2;
            int p = BFORM ? (8 * j1 + k2) : (j1 + 8 * k2);
            v[p] = cmulc<DIR>(v[p], C64(m), S64(m));
        }
    }
    // phase 2: dft8 over j1 for each k2
#pragma unroll
    for (int k2 = 0; k2 < 8; k2++) {
#pragma unroll
        for (int j1 = 0; j1 < 8; j1++) t[j1] = BFORM ? v[8 * j1 + k2] : v[8 * k2 + j1];
        dft8<DIR>(t);
#pragma unroll
        for (int j1 = 0; j1 < 8; j1++) { if (BFORM) v[8 * j1 + k2] = t[j1]; else v[8 * k2 + j1] = t[j1]; }
    }
}

// ---------- global twiddle: v[pos(k)] *= exp(i*th*k), k = 1..63 ----------
// DSPOS: apply at digit-swapped positions. 4 independent 16-step ladders.
template <bool DSPOS>
__device__ __forceinline__ void gtw(cplx* v, float th) {
    float c1, s1;
    __sincosf(th, &s1, &c1);
    float bc[4], bs[4];
    bc[0] = 1.0f; bs[0] = 0.0f;
    __sincosf(16.0f * th, &bs[1], &bc[1]);
    __sincosf(32.0f * th, &bs[2], &bc[2]);
    __sincosf(48.0f * th, &bs[3], &bc[3]);
#pragma unroll
    for (int a = 0; a < 4; a++) {
        float wr = bc[a], wi = bs[a];
#pragma unroll
        for (int b = 0; b < 16; b++) {
            int k = 16 * a + b;
            if (k > 0) {
                int p = DSPOS ? DS(k) : k;
                v[p] = cmulw(v[p], wr, wi);
            }
            float nr = fmaf(wr, c1, -(wi * s1));
            wi = fmaf(wr, s1, wi * c1);
            wr = nr;
        }
    }
}

// ---------- main kernel: four-step 64x64, fwd FFT + D scale + inv FFT ----------
__global__ void __launch_bounds__(NT)
afdf64_kernel(const cplx* __restrict__ x, const cplx* __restrict__ A,
              const cplx* __restrict__ D, cplx* __restrict__ out) {
    __shared__ cplx S[64 * 65];
    const int t = threadIdx.x;
    const size_t base = (size_t)blockIdx.x * FFT_N;

    cplx v[64];

    // load + A scale (elementwise re/im), thread t owns column n1 = t
#pragma unroll
    for (int n2 = 0; n2 < 64; n2++) {
        int c = t + 64 * n2;
        v[n2] = cmulp(x[base + c], A[c]);
    }

    // forward inner FFT over n2 -> F1[k2] at v[DS(k2)]
    fft64<-1, false>(v);
    // global twiddle W4096^{t*k2}
    gtw<true>(v, -6.283185307179586f * (float)t / (float)FFT_N);

    // transpose 1
#pragma unroll
    for (int k2 = 0; k2 < 64; k2++) S[k2 * 65 + t] = v[DS(k2)];
    __syncthreads();
#pragma unroll
    for (int n1 = 0; n1 < 64; n1++) v[n1] = S[t * 65 + n1];
    __syncthreads();

    // forward outer FFT over n1 -> X[t + 64*k1] at v[DS(k1)]
    fft64<-1, false>(v);

    // D scale + 1/N, in registers at DS positions
    {
        const cplx INVN = cpack(1.0f / (float)FFT_N, 1.0f / (float)FFT_N);
#pragma unroll
        for (int k1 = 0; k1 < 64; k1++) {
            int p = DS(k1);
            v[p] = cmulp(cmulp(v[p], D[t + 64 * k1]), INVN);
        }
    }

    // inverse inner FFT over k1 (DS in -> natural out): G'[n2] at v[n2]
    fft64<+1, true>(v);
    // global twiddle W4096^{-t*n2} (inverse sign)
    gtw<false>(v, 6.283185307179586f * (float)t / (float)FFT_N);

    // transpose 2
#pragma unroll
    for (int n2 = 0; n2 < 64; n2++) S[n2 * 65 + t] = v[n2];
    __syncthreads();
#pragma unroll
    for (int k2 = 0; k2 < 64; k2++) v[k2] = S[t * 65 + k2];

    // inverse outer FFT over k2 -> y[t + 64*n1] at v[DS(n1)]
    fft64<+1, false>(v);

    // store (coalesced)
#pragma unroll
    for (int n1 = 0; n1 < 64; n1++) out[base + t + 64 * n1] = v[DS(n1)];
}

extern "C" void kernel_launch(void* const* d_in, const int* in_sizes, int n_in,
                              void* d_out, int out_size) {
    const cplx* x = (const cplx*)d_in[0];
    const cplx* A = (const cplx*)d_in[1];
    const cplx* D = (const cplx*)d_in[2];
    cplx* out = (cplx*)d_out;

    int rows = in_sizes[0] / (FFT_N * 2);   // (B, C, 2) float32
    afdf64_kernel<<<rows, NT>>>(x, A, D, out);
}